// round 5
// baseline (speedup 1.0000x reference)
#include <cuda_runtime.h>
#include <cuda_fp16.h>
#include <cstdint>
#include <type_traits>

// ---------------- problem constants ----------------
#define B_      16
#define Q_      300
#define DMODEL  256
#define NHEADS  8
#define HD      32
#define LV      8400          // 80*80 + 40*40 + 20*20
#define BQ      (B_*Q_)       // 4800
#define MV      (B_*LV)       // 134400 rows of value
#define MT_PAD  4864          // 38*128

// ---------------- scratch (device globals; zero-initialized) ----------------
__device__ __half g_v16[MV * DMODEL];        // projected value, fp16
__device__ __half g_tmp16[MT_PAD * DMODEL];  // sampled heads, fp16; rows>=4800 stay 0
__device__ __half g_wv16[DMODEL * DMODEL];   // Wv  in fp16
__device__ __half g_wo16[DMODEL * DMODEL];   // Wout in fp16
__device__ float  g_off[BQ * 192];
__device__ float  g_attn[BQ * 96];

// ---------------- helpers ----------------
__device__ __forceinline__ uint32_t smem_u32(const void* p) {
    uint32_t a;
    asm("{ .reg .u64 t; cvta.to.shared.u64 t, %1; cvt.u32.u64 %0, t; }" : "=r"(a) : "l"(p));
    return a;
}
__device__ __forceinline__ void ldsm_x4(uint32_t* r, uint32_t addr) {
    asm volatile("ldmatrix.sync.aligned.m8n8.x4.shared.b16 {%0,%1,%2,%3}, [%4];"
                 : "=r"(r[0]), "=r"(r[1]), "=r"(r[2]), "=r"(r[3]) : "r"(addr));
}
__device__ __forceinline__ void ldsm_x4_t(uint32_t* r, uint32_t addr) {
    asm volatile("ldmatrix.sync.aligned.m8n8.x4.trans.shared.b16 {%0,%1,%2,%3}, [%4];"
                 : "=r"(r[0]), "=r"(r[1]), "=r"(r[2]), "=r"(r[3]) : "r"(addr));
}
__device__ __forceinline__ void mma16(float* c, const uint32_t* a, const uint32_t* b) {
    asm volatile(
        "mma.sync.aligned.m16n8k16.row.col.f32.f16.f16.f32 "
        "{%0,%1,%2,%3}, {%4,%5,%6,%7}, {%8,%9}, {%0,%1,%2,%3};\n"
        : "+f"(c[0]), "+f"(c[1]), "+f"(c[2]), "+f"(c[3])
        : "r"(a[0]), "r"(a[1]), "r"(a[2]), "r"(a[3]), "r"(b[0]), "r"(b[1]));
}
__device__ __forceinline__ uint32_t packh2(float x, float y) {
    __half2 h = __floats2half2_rn(x, y);
    return *reinterpret_cast<uint32_t*>(&h);
}

// ---------------- fp16 GEMM geometry ----------------
#define BK       32
#define ASTR     40    // halves per A smem row
#define BSTR     264   // halves per B smem row
#define A_HALVES (128 * ASTR)          // 5120
#define B_HALVES (32 * BSTR)           // 8448
#define SM_A0    0
#define SM_A1    (A_HALVES)
#define SM_B0    (2 * A_HALVES)
#define SM_B1    (2 * A_HALVES + B_HALVES)
#define SM_TOT_H (2 * A_HALVES + 2 * B_HALVES)       // 27136 halves
#define SM_TOT_B (SM_TOT_H * 2)                      // 54272 bytes
// per-warp epilogue staging: 16 rows x 72 halves
#define EPI_STR  72
#define EPI_HALVES 1152

// ============================================================================
// fp32 -> fp16 convert (for Wv / Wout), n multiple of 4
// ============================================================================
__global__ void cvt_fp16(const float* __restrict__ src, __half* __restrict__ dst, int n) {
    int i = (blockIdx.x * blockDim.x + threadIdx.x) * 4;
    if (i < n) {
        float4 v = *reinterpret_cast<const float4*>(src + i);
        uint2 u = make_uint2(packh2(v.x, v.y), packh2(v.z, v.w));
        *reinterpret_cast<uint2*>(dst + i) = u;
    }
}

// ============================================================================
// fp16 tensor-core GEMM: C[M x 256] = A[M x 256] @ W16[256 x 256] + bias.
// Block = 128 x 256 (full N), 8 warps as 2(m) x 4(n), warp 64x64.
// TA in {float, __half}; TC in {__half, float}. fp16-C path repacks via smem
// for fully coalesced 128B stores.
// ============================================================================
template<typename TA, typename TC>
__global__ void __launch_bounds__(256, 1)
gemm_fp16(const TA* __restrict__ A, const __half* __restrict__ W16,
          const float* __restrict__ bias, TC* __restrict__ C, int Mstore) {
    extern __shared__ __half sh[];
    const uint32_t sb = smem_u32(sh);
    const int tid = threadIdx.x, warp = tid >> 5, lane = tid & 31;
    const int wm = warp >> 2, wn = warp & 3;
    const int g = lane >> 2, tg = lane & 3;
    const int m0 = blockIdx.x * 128;

    const int arow = tid >> 1, ac0 = (tid & 1) * 16;   // A: 16 elems / thread
    const int brow = tid >> 3, bc0 = (tid & 7) * 32;   // B: 32 halves / thread

    float acc[4][8][4];
    #pragma unroll
    for (int i = 0; i < 4; i++)
        #pragma unroll
        for (int j = 0; j < 8; j++)
            #pragma unroll
            for (int k = 0; k < 4; k++) acc[i][j][k] = 0.f;

    // ---- prologue: fill stage 0 ----
    {
        if constexpr (std::is_same_v<TA, float>) {
            const float* ap = A + (size_t)(m0 + arow) * 256 + ac0;
            #pragma unroll
            for (int i = 0; i < 4; i++) {
                float4 v = *reinterpret_cast<const float4*>(ap + 4 * i);
                uint2 u = make_uint2(packh2(v.x, v.y), packh2(v.z, v.w));
                *reinterpret_cast<uint2*>(&sh[SM_A0 + arow * ASTR + ac0 + 4 * i]) = u;
            }
        } else {
            const __half* ap = A + (size_t)(m0 + arow) * 256 + ac0;
            #pragma unroll
            for (int i = 0; i < 2; i++)        // 16 halves = 2 x uint4
                *reinterpret_cast<uint4*>(&sh[SM_A0 + arow * ASTR + ac0 + 8 * i]) =
                    *reinterpret_cast<const uint4*>(ap + 8 * i);
        }
        const __half* wp = W16 + (size_t)brow * 256 + bc0;
        #pragma unroll
        for (int i = 0; i < 4; i++)
            *reinterpret_cast<uint4*>(&sh[SM_B0 + brow * BSTR + bc0 + 8 * i]) =
                *reinterpret_cast<const uint4*>(wp + 8 * i);
    }
    __syncthreads();

    const uint32_t a_lrow = (uint32_t)(lane & 15);
    const uint32_t a_kadd = (uint32_t)(lane >> 4) * 8;

    #pragma unroll
    for (int c = 0; c < 8; c++) {
        const int cur = c & 1;
        float4 raf[4]; uint4 rah[2]; uint4 rb[4];
        if (c < 7) {
            const int kc = (c + 1) * BK;
            if constexpr (std::is_same_v<TA, float>) {
                const float* ap = A + (size_t)(m0 + arow) * 256 + kc + ac0;
                #pragma unroll
                for (int i = 0; i < 4; i++)
                    raf[i] = *reinterpret_cast<const float4*>(ap + 4 * i);
            } else {
                const __half* ap = A + (size_t)(m0 + arow) * 256 + kc + ac0;
                #pragma unroll
                for (int i = 0; i < 2; i++)
                    rah[i] = *reinterpret_cast<const uint4*>(ap + 8 * i);
            }
            const __half* wp = W16 + (size_t)(kc + brow) * 256 + bc0;
            #pragma unroll
            for (int i = 0; i < 4; i++)
                rb[i] = *reinterpret_cast<const uint4*>(wp + 8 * i);
        }

        // ---- compute current stage ----
        const uint32_t aB = sb + (cur ? SM_A1 : SM_A0) * 2;
        const uint32_t bB = sb + (cur ? SM_B1 : SM_B0) * 2;
        #pragma unroll
        for (int k16 = 0; k16 < 2; k16++) {
            uint32_t af[4][4], bf[8][2];
            #pragma unroll
            for (int mi = 0; mi < 4; mi++) {
                uint32_t addr = aB + ((wm * 64 + mi * 16 + a_lrow) * ASTR
                                      + k16 * 16 + a_kadd) * 2;
                ldsm_x4(af[mi], addr);
            }
            #pragma unroll
            for (int nq = 0; nq < 4; nq++) {
                uint32_t r[4];
                uint32_t addr = bB + ((k16 * 16 + a_lrow) * BSTR
                                      + wn * 64 + nq * 16 + a_kadd) * 2;
                ldsm_x4_t(r, addr);
                bf[2 * nq][0] = r[0]; bf[2 * nq][1] = r[1];
                bf[2 * nq + 1][0] = r[2]; bf[2 * nq + 1][1] = r[3];
            }
            #pragma unroll
            for (int mi = 0; mi < 4; mi++)
                #pragma unroll
                for (int ni = 0; ni < 8; ni++)
                    mma16(acc[mi][ni], af[mi], bf[ni]);
        }

        if (c < 7) {
            const int nxt = (c + 1) & 1;
            __half* dA = &sh[(nxt ? SM_A1 : SM_A0)];
            __half* dB = &sh[(nxt ? SM_B1 : SM_B0)];
            if constexpr (std::is_same_v<TA, float>) {
                #pragma unroll
                for (int i = 0; i < 4; i++) {
                    uint2 u = make_uint2(packh2(raf[i].x, raf[i].y), packh2(raf[i].z, raf[i].w));
                    *reinterpret_cast<uint2*>(&dA[arow * ASTR + ac0 + 4 * i]) = u;
                }
            } else {
                #pragma unroll
                for (int i = 0; i < 2; i++)
                    *reinterpret_cast<uint4*>(&dA[arow * ASTR + ac0 + 8 * i]) = rah[i];
            }
            #pragma unroll
            for (int i = 0; i < 4; i++)
                *reinterpret_cast<uint4*>(&dB[brow * BSTR + bc0 + 8 * i]) = rb[i];
            __syncthreads();
        }
    }

    // ---- epilogue ----
    float2 bb[8];
    #pragma unroll
    for (int ni = 0; ni < 8; ni++)
        bb[ni] = *reinterpret_cast<const float2*>(&bias[wn * 64 + ni * 8 + 2 * tg]);

    if constexpr (std::is_same_v<TC, __half>) {
        __syncthreads();                         // all MMA smem reads done; reuse smem
        __half* buf = &sh[warp * EPI_HALVES];
        #pragma unroll
        for (int mi = 0; mi < 4; mi++) {
            #pragma unroll
            for (int ni = 0; ni < 8; ni++) {
                const int cc = ni * 8 + 2 * tg;
                __half2 lo = __floats2half2_rn(acc[mi][ni][0] + bb[ni].x,
                                               acc[mi][ni][1] + bb[ni].y);
                __half2 hi = __floats2half2_rn(acc[mi][ni][2] + bb[ni].x,
                                               acc[mi][ni][3] + bb[ni].y);
                *reinterpret_cast<__half2*>(&buf[g * EPI_STR + cc]) = lo;
                *reinterpret_cast<__half2*>(&buf[(g + 8) * EPI_STR + cc]) = hi;
            }
            __syncwarp();
            #pragma unroll
            for (int p = 0; p < 4; p++) {
                const int row = p * 4 + (lane >> 3);
                const int ch  = lane & 7;
                uint4 v = *reinterpret_cast<const uint4*>(&buf[row * EPI_STR + ch * 8]);
                const int grow = m0 + wm * 64 + mi * 16 + row;
                if (grow < Mstore)
                    *reinterpret_cast<uint4*>(
                        &C[(size_t)grow * 256 + wn * 64 + ch * 8]) = v;
            }
            __syncwarp();
        }
    } else {
        #pragma unroll
        for (int mi = 0; mi < 4; mi++) {
            const int r0 = m0 + wm * 64 + mi * 16 + g;
            const int r1 = r0 + 8;
            #pragma unroll
            for (int ni = 0; ni < 8; ni++) {
                const int cc = wn * 64 + ni * 8 + 2 * tg;
                if (r0 < Mstore)
                    *reinterpret_cast<float2*>(&C[(size_t)r0 * 256 + cc]) =
                        make_float2(acc[mi][ni][0] + bb[ni].x, acc[mi][ni][1] + bb[ni].y);
                if (r1 < Mstore)
                    *reinterpret_cast<float2*>(&C[(size_t)r1 * 256 + cc]) =
                        make_float2(acc[mi][ni][2] + bb[ni].x, acc[mi][ni][3] + bb[ni].y);
            }
        }
    }
}

// ============================================================================
// Exact fp32 GEMM, 64x64 tile, 4x4 per thread (offsets; coordinate precision)
// ============================================================================
__global__ __launch_bounds__(256, 3)
void fgemm64x64(const float* __restrict__ A, const float* __restrict__ Bm,
                const float* __restrict__ bias, float* __restrict__ C, int N) {
    __shared__ float As[64 * 36];
    __shared__ float Bs[32 * 68];
    const int tid = threadIdx.x;
    const int n0 = blockIdx.x * 64;
    const int m0 = blockIdx.y * 64;
    const int ty = tid >> 4, tx = tid & 15;
    const int arow = tid >> 3, acol = (tid & 7) * 4;
    const int brow = tid >> 3, bcol = (tid & 7) * 8;

    float acc[4][4] = {};
    for (int kc = 0; kc < 256; kc += 32) {
        #pragma unroll
        for (int i = 0; i < 2; i++) {
            const float4 va = *reinterpret_cast<const float4*>(
                A + (size_t)(m0 + arow + i * 32) * 256 + kc + acol);
            *reinterpret_cast<float4*>(&As[(arow + i * 32) * 36 + acol]) = va;
        }
        #pragma unroll
        for (int i = 0; i < 2; i++) {
            const float4 vb = *reinterpret_cast<const float4*>(
                Bm + (size_t)(kc + brow) * N + n0 + bcol + 4 * i);
            *reinterpret_cast<float4*>(&Bs[brow * 68 + bcol + 4 * i]) = vb;
        }
        __syncthreads();
        #pragma unroll
        for (int kk = 0; kk < 32; kk++) {
            float a0 = As[(ty * 4 + 0) * 36 + kk];
            float a1 = As[(ty * 4 + 1) * 36 + kk];
            float a2 = As[(ty * 4 + 2) * 36 + kk];
            float a3 = As[(ty * 4 + 3) * 36 + kk];
            float4 bv = *reinterpret_cast<const float4*>(&Bs[kk * 68 + tx * 4]);
            acc[0][0] += a0 * bv.x; acc[0][1] += a0 * bv.y; acc[0][2] += a0 * bv.z; acc[0][3] += a0 * bv.w;
            acc[1][0] += a1 * bv.x; acc[1][1] += a1 * bv.y; acc[1][2] += a1 * bv.z; acc[1][3] += a1 * bv.w;
            acc[2][0] += a2 * bv.x; acc[2][1] += a2 * bv.y; acc[2][2] += a2 * bv.z; acc[2][3] += a2 * bv.w;
            acc[3][0] += a3 * bv.x; acc[3][1] += a3 * bv.y; acc[3][2] += a3 * bv.z; acc[3][3] += a3 * bv.w;
        }
        __syncthreads();
    }
    const float4 bv = *reinterpret_cast<const float4*>(&bias[n0 + tx * 4]);
    #pragma unroll
    for (int i = 0; i < 4; i++) {
        float4 v = make_float4(acc[i][0] + bv.x, acc[i][1] + bv.y,
                               acc[i][2] + bv.z, acc[i][3] + bv.w);
        *reinterpret_cast<float4*>(&C[(size_t)(m0 + ty * 4 + i) * N + n0 + tx * 4]) = v;
    }
}

// ============================================================================
// Exact fp32 GEMM 64x32 (attn logits)
// ============================================================================
__global__ __launch_bounds__(256, 4)
void fgemm64x32(const float* __restrict__ A, const float* __restrict__ Bm,
                const float* __restrict__ bias, float* __restrict__ C, int N) {
    __shared__ float As[64 * 36];
    __shared__ float Bs[32 * 36];
    const int tid = threadIdx.x;
    const int n0 = blockIdx.x * 32;
    const int m0 = blockIdx.y * 64;
    const int ty = tid >> 4, tx = tid & 15;
    const int arow = tid >> 3, acol = (tid & 7) * 4;
    float acc[4][2] = {};
    for (int kc = 0; kc < 256; kc += 32) {
        #pragma unroll
        for (int i = 0; i < 2; i++) {
            const float4 va = *reinterpret_cast<const float4*>(
                A + (size_t)(m0 + arow + i * 32) * 256 + kc + acol);
            *reinterpret_cast<float4*>(&As[(arow + i * 32) * 36 + acol]) = va;
        }
        {
            const float4 vb = *reinterpret_cast<const float4*>(
                Bm + (size_t)(kc + arow) * N + n0 + acol);
            *reinterpret_cast<float4*>(&Bs[arow * 36 + acol]) = vb;
        }
        __syncthreads();
        #pragma unroll
        for (int kk = 0; kk < 32; kk++) {
            float a0 = As[(ty * 4 + 0) * 36 + kk];
            float a1 = As[(ty * 4 + 1) * 36 + kk];
            float a2 = As[(ty * 4 + 2) * 36 + kk];
            float a3 = As[(ty * 4 + 3) * 36 + kk];
            float2 bv = *reinterpret_cast<const float2*>(&Bs[kk * 36 + tx * 2]);
            acc[0][0] += a0 * bv.x;  acc[0][1] += a0 * bv.y;
            acc[1][0] += a1 * bv.x;  acc[1][1] += a1 * bv.y;
            acc[2][0] += a2 * bv.x;  acc[2][1] += a2 * bv.y;
            acc[3][0] += a3 * bv.x;  acc[3][1] += a3 * bv.y;
        }
        __syncthreads();
    }
    const float b0 = bias[n0 + tx * 2], b1 = bias[n0 + tx * 2 + 1];
    #pragma unroll
    for (int i = 0; i < 4; i++) {
        float2 v = make_float2(acc[i][0] + b0, acc[i][1] + b1);
        *reinterpret_cast<float2*>(&C[(size_t)(m0 + ty * 4 + i) * N + n0 + tx * 2]) = v;
    }
}

// ============================================================================
// Deformable sampling: owner-lane precompute + fp16 gathers.
// ============================================================================
__global__ __launch_bounds__(256)
void sample_kernel(const float* __restrict__ off, const float* __restrict__ attn,
                   const float* __restrict__ rp, const __half* __restrict__ v,
                   __half* __restrict__ tmp) {
    const int bq   = blockIdx.x;
    const int h    = threadIdx.x >> 5;
    const int lane = threadIdx.x & 31;
    const int b    = bq / Q_;

    const float refx = rp[bq * 4 + 0];
    const float refy = rp[bq * 4 + 1];

    float logit = -1e30f, px = 0.f, py = 0.f;
    int W = 1, start = 0;
    if (lane < 12) {
        logit = attn[bq * 96 + h * 12 + lane];
        const float ox = off[bq * 192 + h * 24 + lane * 2 + 0];
        const float oy = off[bq * 192 + h * 24 + lane * 2 + 1];
        const int lvl = lane >> 2;
        W     = (lvl == 0) ? 80 : ((lvl == 1) ? 40 : 20);
        start = (lvl == 0) ? 0 : ((lvl == 1) ? 6400 : 8000);
        const float Wf = (float)W;
        const float ptsx = fminf(fmaxf(refx + ox, 0.f), 1.f);
        const float ptsy = fminf(fmaxf(refy + oy, 0.f), 1.f);
        px = ptsx * Wf - 0.5f;
        py = ptsy * Wf - 0.5f;
    }
    // softmax over 12 valid lanes
    float mx = logit;
    #pragma unroll
    for (int s = 16; s > 0; s >>= 1) mx = fmaxf(mx, __shfl_xor_sync(0xffffffffu, mx, s));
    float e = (lane < 12) ? expf(logit - mx) : 0.f;
    float ssum = e;
    #pragma unroll
    for (int s = 16; s > 0; s >>= 1) ssum += __shfl_xor_sync(0xffffffffu, ssum, s);
    const float wgt = e / ssum;

    // owner-lane corner precompute
    int i00 = 0, i01 = 0, i10 = 0, i11 = 0;
    float w00 = 0.f, w01 = 0.f, w10 = 0.f, w11 = 0.f;
    if (lane < 12) {
        const float x0f = floorf(px), y0f = floorf(py);
        const float fx = px - x0f, fy = py - y0f;
        const int x0 = (int)x0f, y0 = (int)y0f;
        const int x1 = x0 + 1, y1 = y0 + 1;
        const bool vx0 = (unsigned)x0 < (unsigned)W, vx1 = (unsigned)x1 < (unsigned)W;
        const bool vy0 = (unsigned)y0 < (unsigned)W, vy1 = (unsigned)y1 < (unsigned)W;
        const int x0c = min(max(x0, 0), W - 1), x1c = min(max(x1, 0), W - 1);
        const int y0c = min(max(y0, 0), W - 1), y1c = min(max(y1, 0), W - 1);
        i00 = start + y0c * W + x0c;  i01 = start + y0c * W + x1c;
        i10 = start + y1c * W + x0c;  i11 = start + y1c * W + x1c;
        w00 = wgt * (1.f - fx) * (1.f - fy) * (float)(vx0 && vy0);
        w01 = wgt * fx * (1.f - fy) * (float)(vx1 && vy0);
        w10 = wgt * (1.f - fx) * fy * (float)(vx0 && vy1);
        w11 = wgt * fx * fy * (float)(vx1 && vy1);
    }

    const __half* vb = v + (size_t)b * LV * DMODEL + h * HD + lane;
    float acc = 0.f;
    #pragma unroll
    for (int j = 0; j < 12; j++) {
        const int   a00 = __shfl_sync(0xffffffffu, i00, j);
        const int   a01 = __shfl_sync(0xffffffffu, i01, j);
        const int   a10 = __shfl_sync(0xffffffffu, i10, j);
        const int   a11 = __shfl_sync(0xffffffffu, i11, j);
        const float q00 = __shfl_sync(0xffffffffu, w00, j);
        const float q01 = __shfl_sync(0xffffffffu, w01, j);
        const float q10 = __shfl_sync(0xffffffffu, w10, j);
        const float q11 = __shfl_sync(0xffffffffu, w11, j);
        acc += q00 * __half2float(vb[(size_t)a00 * DMODEL]);
        acc += q01 * __half2float(vb[(size_t)a01 * DMODEL]);
        acc += q10 * __half2float(vb[(size_t)a10 * DMODEL]);
        acc += q11 * __half2float(vb[(size_t)a11 * DMODEL]);
    }

    tmp[(size_t)bq * DMODEL + h * HD + lane] = __float2half(acc);
}

// ============================================================================
extern "C" void kernel_launch(void* const* d_in, const int* in_sizes, int n_in,
                              void* d_out, int out_size) {
    const float* query = (const float*)d_in[0];
    const float* rp    = (const float*)d_in[1];
    const float* value = (const float*)d_in[2];
    const float* Wv    = (const float*)d_in[3];
    const float* bv    = (const float*)d_in[4];
    const float* Woff  = (const float*)d_in[5];
    const float* boff  = (const float*)d_in[6];
    const float* Wattn = (const float*)d_in[7];
    const float* battn = (const float*)d_in[8];
    const float* Wout  = (const float*)d_in[9];
    const float* bout  = (const float*)d_in[10];
    float* out = (float*)d_out;

    __half *pv16, *ptmp16, *pwv16, *pwo16;
    float *poff, *pattn;
    cudaGetSymbolAddress((void**)&pv16,   g_v16);
    cudaGetSymbolAddress((void**)&ptmp16, g_tmp16);
    cudaGetSymbolAddress((void**)&pwv16,  g_wv16);
    cudaGetSymbolAddress((void**)&pwo16,  g_wo16);
    cudaGetSymbolAddress((void**)&poff,   g_off);
    cudaGetSymbolAddress((void**)&pattn,  g_attn);

    cudaFuncSetAttribute(gemm_fp16<float, __half>,
                         cudaFuncAttributeMaxDynamicSharedMemorySize, SM_TOT_B);
    cudaFuncSetAttribute(gemm_fp16<__half, float>,
                         cudaFuncAttributeMaxDynamicSharedMemorySize, SM_TOT_B);

    // 0) weights -> fp16 (tiny)
    cvt_fp16<<<64, 256>>>(Wv, pwv16, DMODEL * DMODEL);
    cvt_fp16<<<64, 256>>>(Wout, pwo16, DMODEL * DMODEL);
    // 1) v = value @ Wv + bv   -> fp16, coalesced repack stores
    gemm_fp16<float, __half><<<MV / 128, 256, SM_TOT_B>>>(value, pwv16, bv, pv16, MV);
    // 2) offsets = query @ Woff + boff   (exact fp32)
    fgemm64x64<<<dim3(3, BQ / 64), 256>>>(query, Woff, boff, poff, 192);
    // 3) attn logits = query @ Wattn + battn   (exact fp32)
    fgemm64x32<<<dim3(3, BQ / 64), 256>>>(query, Wattn, battn, pattn, 96);
    // 4) softmax + deformable bilinear sampling -> g_tmp16
    sample_kernel<<<BQ, 256>>>(poff, pattn, rp, pv16, ptmp16);
    // 5) out = tmp @ Wout + bout   (fp16 A, fp32 C, guarded)
    gemm_fp16<__half, float><<<MT_PAD / 128, 256, SM_TOT_B>>>(ptmp16, pwo16, bout, out, BQ);
}